// round 5
// baseline (speedup 1.0000x reference)
#include <cuda_runtime.h>
#include <cuda_fp16.h>

#define NN     50000
#define VOCAB  512
#define EE     600000
#define D      128
#define D4     32
#define LN_EPS 1e-5f

// ---------------- device scratch (zero-initialized at load; each run restores zeros) ----
__device__ __align__(16) float g_deg [NN];       // sum of incoming ew (no self loop)
__device__ __align__(16) int   g_cnt [NN];       // in-degree histogram
__device__ __align__(16) int   g_off [NN];       // CSR offsets
__device__ __align__(16) int   g_pos [NN];       // fill cursor; == deg after fill
__device__ __align__(16) int2  g_adj [EE];       // (src node, coef bits)
__device__ __align__(16) int2  g_adj1[EE];       // (vocab id,  coef bits)
__device__ __align__(16) float g_x   [NN * D];   // layer-1 output (fp32)
__device__ __align__(16) uint2 g_h16 [NN * D4];  // h2 = x @ W2, fp16 packed (4 halves/lane)
__device__ __align__(16) uint2 g_G1h [VOCAB * D4]; // G1 = emb @ W1, fp16 packed

// ---------------- per-edge: degree + histogram (g_deg/g_cnt start at 0) ----------------
__global__ void k_count(const int* __restrict__ col, const float* __restrict__ ew, int E) {
    int e = blockIdx.x * blockDim.x + threadIdx.x;
    if (e < E) {
        int c = col[e];
        atomicAdd(&g_deg[c], ew[e]);
        atomicAdd(&g_cnt[c], 1);
    }
}

// ---------------- single-block exclusive scan of g_cnt -> g_off; re-zero g_cnt --------
#define SCAN_PER_T 49   // 1024 * 49 = 50176 >= NN
__global__ void __launch_bounds__(1024) k_scan(int n) {
    __shared__ int wsum[32];
    int t = threadIdx.x;
    int base = t * SCAN_PER_T;
    int lim = n - base; if (lim < 0) lim = 0; if (lim > SCAN_PER_T) lim = SCAN_PER_T;
    int s = 0;
    for (int j = 0; j < lim; j++) s += g_cnt[base + j];
    int lane = t & 31, wid = t >> 5;
    int ss = s;
#pragma unroll
    for (int o = 1; o < 32; o <<= 1) {
        int u = __shfl_up_sync(0xFFFFFFFFu, ss, o);
        if (lane >= o) ss += u;
    }
    if (lane == 31) wsum[wid] = ss;
    __syncthreads();
    if (wid == 0) {
        int w = wsum[lane];
        int sw = w;
#pragma unroll
        for (int o = 1; o < 32; o <<= 1) {
            int u = __shfl_up_sync(0xFFFFFFFFu, sw, o);
            if (lane >= o) sw += u;
        }
        wsum[lane] = sw - w;     // exclusive warp offsets
    }
    __syncthreads();
    int run = wsum[wid] + (ss - s);
    for (int j = 0; j < lim; j++) {
        int c = g_cnt[base + j];
        g_off[base + j] = run;
        run += c;
        g_cnt[base + j] = 0;     // restore for next replay
    }
}

// ---------------- CSR fill; coef computed inline from g_deg ----------------
__global__ void k_fill(const int* __restrict__ rows, const int* __restrict__ cols,
                       const float* __restrict__ ew, const int* __restrict__ nid, int E) {
    int e = blockIdx.x * blockDim.x + threadIdx.x;
    if (e >= E) return;
    int r = rows[e], c = cols[e];
    float coef = rsqrtf(g_deg[r] + 1.0f) * ew[e] * rsqrtf(g_deg[c] + 1.0f);
    int p = g_off[c] + atomicAdd(&g_pos[c], 1);
    int cb = __float_as_int(coef);
    g_adj [p] = make_int2(r,      cb);
    g_adj1[p] = make_int2(nid[r], cb);
}

// ---------------- helpers ----------------
__device__ __forceinline__ float4 unpack_h4(uint2 v) {
    __half2 a = *(__half2*)&v.x;
    __half2 b = *(__half2*)&v.y;
    float2 f01 = __half22float2(a), f23 = __half22float2(b);
    return make_float4(f01.x, f01.y, f23.x, f23.y);
}

union H2U { __half2 h; unsigned int u; };

// ------- layer 1 fused: aggregate from fp16 G1 table (L1-resident) + residual(emb) + LN
__global__ void k_agg1(const int* __restrict__ nid, const float* __restrict__ emb,
                       const float* __restrict__ b,
                       const float* __restrict__ gamma, const float* __restrict__ beta,
                       float* __restrict__ out, int n) {
    int gt = blockIdx.x * blockDim.x + threadIdx.x;
    int node = gt >> 5, lane = gt & 31;
    if (node >= n) return;
    int id = nid[node];
    float cself = 1.0f / (1.0f + g_deg[node]);
    float4 hv = unpack_h4(g_G1h[id * D4 + lane]);
    float4 bv = ((const float4*)b)[lane];
    float4 acc = make_float4(fmaf(cself, hv.x, bv.x), fmaf(cself, hv.y, bv.y),
                             fmaf(cself, hv.z, bv.z), fmaf(cself, hv.w, bv.w));
    int off = g_off[node], deg = g_pos[node];
    const int2* __restrict__ adj = g_adj1 + off;
    int j = 0;
    for (; j + 3 < deg; j += 4) {
        int2 a0 = adj[j], a1 = adj[j+1], a2 = adj[j+2], a3 = adj[j+3];
        float4 h0 = unpack_h4(g_G1h[a0.x * D4 + lane]);
        float4 h1 = unpack_h4(g_G1h[a1.x * D4 + lane]);
        float4 h2 = unpack_h4(g_G1h[a2.x * D4 + lane]);
        float4 h3 = unpack_h4(g_G1h[a3.x * D4 + lane]);
        float c0 = __int_as_float(a0.y), c1 = __int_as_float(a1.y);
        float c2 = __int_as_float(a2.y), c3 = __int_as_float(a3.y);
        acc.x = fmaf(c0,h0.x,acc.x); acc.y = fmaf(c0,h0.y,acc.y); acc.z = fmaf(c0,h0.z,acc.z); acc.w = fmaf(c0,h0.w,acc.w);
        acc.x = fmaf(c1,h1.x,acc.x); acc.y = fmaf(c1,h1.y,acc.y); acc.z = fmaf(c1,h1.z,acc.z); acc.w = fmaf(c1,h1.w,acc.w);
        acc.x = fmaf(c2,h2.x,acc.x); acc.y = fmaf(c2,h2.y,acc.y); acc.z = fmaf(c2,h2.z,acc.z); acc.w = fmaf(c2,h2.w,acc.w);
        acc.x = fmaf(c3,h3.x,acc.x); acc.y = fmaf(c3,h3.y,acc.y); acc.z = fmaf(c3,h3.z,acc.z); acc.w = fmaf(c3,h3.w,acc.w);
    }
    for (; j < deg; j++) {
        int2 a0 = adj[j];
        float c0 = __int_as_float(a0.y);
        float4 h0 = unpack_h4(g_G1h[a0.x * D4 + lane]);
        acc.x = fmaf(c0,h0.x,acc.x); acc.y = fmaf(c0,h0.y,acc.y); acc.z = fmaf(c0,h0.z,acc.z); acc.w = fmaf(c0,h0.w,acc.w);
    }
    float4 xv = ((const float4*)emb)[id * D4 + lane];
    acc.x += xv.x; acc.y += xv.y; acc.z += xv.z; acc.w += xv.w;
    float s  = acc.x + acc.y + acc.z + acc.w;
    float sq = acc.x*acc.x + acc.y*acc.y + acc.z*acc.z + acc.w*acc.w;
#pragma unroll
    for (int o = 16; o > 0; o >>= 1) {
        s  += __shfl_xor_sync(0xFFFFFFFFu, s,  o);
        sq += __shfl_xor_sync(0xFFFFFFFFu, sq, o);
    }
    float mu  = s * (1.f / D);
    float var = sq * (1.f / D) - mu * mu;
    float rs  = rsqrtf(var + LN_EPS);
    float4 g  = ((const float4*)gamma)[lane];
    float4 be = ((const float4*)beta )[lane];
    float4 o;
    o.x = (acc.x - mu) * rs * g.x + be.x;
    o.y = (acc.y - mu) * rs * g.y + be.y;
    o.z = (acc.z - mu) * rs * g.z + be.z;
    o.w = (acc.w - mu) * rs * g.w + be.w;
    ((float4*)out)[node * D4 + lane] = o;
}

// ------- layer 2 fused: gather fp16 h + residual + LN; epilogue restores zeros -------
__global__ void k_agg2(const float* __restrict__ x, const float* __restrict__ b,
                       const float* __restrict__ gamma, const float* __restrict__ beta,
                       float* __restrict__ out, int n) {
    int gt = blockIdx.x * blockDim.x + threadIdx.x;
    int node = gt >> 5, lane = gt & 31;
    if (node >= n) return;
    float cself = 1.0f / (1.0f + g_deg[node]);
    float4 hv = unpack_h4(g_h16[node * D4 + lane]);
    float4 bv = ((const float4*)b)[lane];
    float4 acc = make_float4(fmaf(cself, hv.x, bv.x), fmaf(cself, hv.y, bv.y),
                             fmaf(cself, hv.z, bv.z), fmaf(cself, hv.w, bv.w));
    int off = g_off[node], deg = g_pos[node];
    const int2* __restrict__ adj = g_adj + off;
    int j = 0;
    for (; j + 3 < deg; j += 4) {
        int2 a0 = adj[j], a1 = adj[j+1], a2 = adj[j+2], a3 = adj[j+3];
        float4 h0 = unpack_h4(g_h16[a0.x * D4 + lane]);
        float4 h1 = unpack_h4(g_h16[a1.x * D4 + lane]);
        float4 h2 = unpack_h4(g_h16[a2.x * D4 + lane]);
        float4 h3 = unpack_h4(g_h16[a3.x * D4 + lane]);
        float c0 = __int_as_float(a0.y), c1 = __int_as_float(a1.y);
        float c2 = __int_as_float(a2.y), c3 = __int_as_float(a3.y);
        acc.x = fmaf(c0,h0.x,acc.x); acc.y = fmaf(c0,h0.y,acc.y); acc.z = fmaf(c0,h0.z,acc.z); acc.w = fmaf(c0,h0.w,acc.w);
        acc.x = fmaf(c1,h1.x,acc.x); acc.y = fmaf(c1,h1.y,acc.y); acc.z = fmaf(c1,h1.z,acc.z); acc.w = fmaf(c1,h1.w,acc.w);
        acc.x = fmaf(c2,h2.x,acc.x); acc.y = fmaf(c2,h2.y,acc.y); acc.z = fmaf(c2,h2.z,acc.z); acc.w = fmaf(c2,h2.w,acc.w);
        acc.x = fmaf(c3,h3.x,acc.x); acc.y = fmaf(c3,h3.y,acc.y); acc.z = fmaf(c3,h3.z,acc.z); acc.w = fmaf(c3,h3.w,acc.w);
    }
    for (; j < deg; j++) {
        int2 a0 = adj[j];
        float c0 = __int_as_float(a0.y);
        float4 h0 = unpack_h4(g_h16[a0.x * D4 + lane]);
        acc.x = fmaf(c0,h0.x,acc.x); acc.y = fmaf(c0,h0.y,acc.y); acc.z = fmaf(c0,h0.z,acc.z); acc.w = fmaf(c0,h0.w,acc.w);
    }
    float4 xv = ((const float4*)x)[node * D4 + lane];
    acc.x += xv.x; acc.y += xv.y; acc.z += xv.z; acc.w += xv.w;
    float s  = acc.x + acc.y + acc.z + acc.w;
    float sq = acc.x*acc.x + acc.y*acc.y + acc.z*acc.z + acc.w*acc.w;
#pragma unroll
    for (int o = 16; o > 0; o >>= 1) {
        s  += __shfl_xor_sync(0xFFFFFFFFu, s,  o);
        sq += __shfl_xor_sync(0xFFFFFFFFu, sq, o);
    }
    float mu  = s * (1.f / D);
    float var = sq * (1.f / D) - mu * mu;
    float rs  = rsqrtf(var + LN_EPS);
    float4 g  = ((const float4*)gamma)[lane];
    float4 be = ((const float4*)beta )[lane];
    float4 o;
    o.x = (acc.x - mu) * rs * g.x + be.x;
    o.y = (acc.y - mu) * rs * g.y + be.y;
    o.z = (acc.z - mu) * rs * g.z + be.z;
    o.w = (acc.w - mu) * rs * g.w + be.w;
    ((float4*)out)[node * D4 + lane] = o;
    if (lane == 0) {                 // restore replay-invariant state
        g_deg[node] = 0.0f;
        g_pos[node] = 0;
    }
}

// ---------------- GEMM: H(fp16) = X(fp32) @ W with packed fma.rn.f32x2 ----------------
typedef unsigned long long ull;

__device__ __forceinline__ ull pk2(float a) {
    ull r; asm("mov.b64 %0, {%1, %1};" : "=l"(r) : "f"(a)); return r;
}
__device__ __forceinline__ void fma2(ull& d, ull a, ull b) {
    asm("fma.rn.f32x2 %0, %1, %2, %0;" : "+l"(d) : "l"(a), "l"(b));
}

#define XS_PITCH 136
#define GEMM_SMEM (64 * XS_PITCH * 4 + 128 * 128 * 4)

__global__ void __launch_bounds__(256) k_gemm(const float* __restrict__ X,
                                              const float* __restrict__ W,
                                              uint2* __restrict__ H, int n) {
    extern __shared__ float smem[];
    float* Xs = smem;                    // [64][XS_PITCH]
    float* Ws = smem + 64 * XS_PITCH;    // [128][128]

    int t  = threadIdx.x;
    int m0 = blockIdx.x * 64;

    const float4* W4  = (const float4*)W;
    float4*       Ws4 = (float4*)Ws;
#pragma unroll
    for (int i = 0; i < 16; i++) Ws4[t + i * 256] = W4[t + i * 256];

#pragma unroll
    for (int i = 0; i < 8; i++) {
        int idx = t + i * 256;
        int r = idx >> 5, kc = idx & 31;
        float4 v = make_float4(0.f, 0.f, 0.f, 0.f);
        if (m0 + r < n) v = ((const float4*)X)[(m0 + r) * D4 + kc];
        *(float4*)&Xs[r * XS_PITCH + kc * 4] = v;
    }
    __syncthreads();

    int cg = t & 15;
    int rg = t >> 4;

    ull acc[4][4];
#pragma unroll
    for (int i = 0; i < 4; i++)
#pragma unroll
        for (int j = 0; j < 4; j++) acc[i][j] = 0ull;

#pragma unroll 2
    for (int k0 = 0; k0 < D; k0 += 4) {
        float4 A[4];
#pragma unroll
        for (int i = 0; i < 4; i++)
            A[i] = *(const float4*)&Xs[(rg * 4 + i) * XS_PITCH + k0];
#pragma unroll
        for (int kk = 0; kk < 4; kk++) {
            ulonglong2 w0 = *(const ulonglong2*)&Ws[(k0 + kk) * D + cg * 4];
            ulonglong2 w1 = *(const ulonglong2*)&Ws[(k0 + kk) * D + 64 + cg * 4];
#pragma unroll
            for (int i = 0; i < 4; i++) {
                float av = (kk == 0) ? A[i].x : (kk == 1) ? A[i].y
                         : (kk == 2) ? A[i].z : A[i].w;
                ull ap = pk2(av);
                fma2(acc[i][0], ap, w0.x);
                fma2(acc[i][1], ap, w0.y);
                fma2(acc[i][2], ap, w1.x);
                fma2(acc[i][3], ap, w1.y);
            }
        }
    }

    union Cv { ull u; float2 f; };
#pragma unroll
    for (int i = 0; i < 4; i++) {
        int row = m0 + rg * 4 + i;
        if (row < n) {
            Cv c0, c1, c2, c3;
            c0.u = acc[i][0]; c1.u = acc[i][1]; c2.u = acc[i][2]; c3.u = acc[i][3];
            H2U p0, p1, p2, p3;
            p0.h = __floats2half2_rn(c0.f.x, c0.f.y);
            p1.h = __floats2half2_rn(c1.f.x, c1.f.y);
            p2.h = __floats2half2_rn(c2.f.x, c2.f.y);
            p3.h = __floats2half2_rn(c3.f.x, c3.f.y);
            uint2 o0, o1;
            o0.x = p0.u; o0.y = p1.u;
            o1.x = p2.u; o1.y = p3.u;
            H[row * D4 + cg]      = o0;
            H[row * D4 + 16 + cg] = o1;
        }
    }
}

// ---------------- host launch ----------------
extern "C" void kernel_launch(void* const* d_in, const int* in_sizes, int n_in,
                              void* d_out, int out_size) {
    const int*   node_ids = (const int*)  d_in[0];
    const int*   edge_idx = (const int*)  d_in[1];
    const float* edge_w   = (const float*)d_in[2];
    const float* emb      = (const float*)d_in[3];
    const float* W1       = (const float*)d_in[4];
    const float* b1       = (const float*)d_in[5];
    const float* W2       = (const float*)d_in[6];
    const float* b2       = (const float*)d_in[7];
    const float* gamma1   = (const float*)d_in[8];
    const float* beta1    = (const float*)d_in[9];
    const float* gamma2   = (const float*)d_in[10];
    const float* beta2    = (const float*)d_in[11];
    float* out = (float*)d_out;

    const int n = in_sizes[0];
    const int E = in_sizes[1] / 2;
    const int* rows = edge_idx;
    const int* cols = edge_idx + E;

    static bool attr_done = false;
    if (!attr_done) {
        cudaFuncSetAttribute(k_gemm, cudaFuncAttributeMaxDynamicSharedMemorySize, GEMM_SMEM);
        attr_done = true;
    }

    float *d_x;
    uint2 *d_h16, *d_G1h;
    cudaGetSymbolAddress((void**)&d_x,   g_x);
    cudaGetSymbolAddress((void**)&d_h16, g_h16);
    cudaGetSymbolAddress((void**)&d_G1h, g_G1h);

    const int nodeBlocks = (n * 32 + 255) / 256;

    // CSR build (3 launches; relies on zeros restored at end of previous run)
    k_count<<<(E + 255) / 256, 256>>>(cols, edge_w, E);
    k_scan <<<1, 1024>>>(n);
    k_fill <<<(E + 255) / 256, 256>>>(rows, cols, edge_w, node_ids, E);

    // G1 = emb @ W1  (fp16 out)
    k_gemm <<<(VOCAB + 63) / 64, 256, GEMM_SMEM>>>(emb, W1, d_G1h, VOCAB);

    // layer 1 (fused gather from L1-resident fp16 table)
    k_agg1 <<<nodeBlocks, 256>>>(node_ids, emb, b1, gamma1, beta1, d_x, n);

    // layer 2
    k_gemm <<<(n + 63) / 64, 256, GEMM_SMEM>>>(d_x, W2, d_h16, n);
    k_agg2 <<<nodeBlocks, 256>>>(d_x, b2, gamma2, beta2, out, n);
}

// round 6
// speedup vs baseline: 1.3737x; 1.3737x over previous
#include <cuda_runtime.h>
#include <cuda_fp16.h>

#define NN     50000
#define VOCAB  512
#define EE     600000
#define D      128
#define D4     32
#define LN_EPS 1e-5f

// ---------------- device scratch (zero-initialized at load; each run restores zeros) ----
__device__ __align__(16) float2 g_degcnt[NN];    // .x = sum of incoming ew, .y = in-degree
__device__ __align__(16) int    g_off [NN];      // CSR offsets
__device__ __align__(16) int    g_pos [NN];      // fill cursor; == deg after fill
__device__ __align__(16) int2   g_adj [EE];      // (src node, coef bits)
__device__ __align__(16) int2   g_adj1[EE];      // (vocab id,  coef bits)
__device__ __align__(16) float  g_x   [NN * D];  // layer-1 output (fp32)
__device__ __align__(16) uint2  g_h16 [NN * D4]; // h2 = x @ W2, fp16 packed
__device__ __align__(16) uint2  g_G1h [VOCAB * D4]; // G1 = emb @ W1, fp16 packed

// ---------------- per-edge: degree + histogram via ONE vector atomic ----------------
__global__ void k_count(const int* __restrict__ col, const float* __restrict__ ew, int E) {
    int e = blockIdx.x * blockDim.x + threadIdx.x;
    if (e < E) {
        int c = col[e];
        atomicAdd(&g_degcnt[c], make_float2(ew[e], 1.0f));
    }
}

// ------- single-block COALESCED exclusive scan of counts -> g_off -------
// warp w owns contiguous [w*1568, (w+1)*1568); chunks of 32 consecutive elems.
#define WARP_ELEMS 1568   // 49 * 32 ; 32 warps * 1568 = 50176 >= NN
__global__ void __launch_bounds__(1024) k_scan(int n) {
    __shared__ int woff[32];
    int t = threadIdx.x, lane = t & 31, w = t >> 5;
    int base = w * WARP_ELEMS;

    // pass 1: warp total (coalesced)
    int tot = 0;
#pragma unroll
    for (int j = 0; j < 49; j++) {
        int i = base + j * 32 + lane;
        tot += (i < n) ? (int)g_degcnt[i].y : 0;
    }
#pragma unroll
    for (int o = 16; o > 0; o >>= 1) tot += __shfl_xor_sync(0xFFFFFFFFu, tot, o);
    if (lane == 0) woff[w] = tot;
    __syncthreads();
    if (w == 0) {
        int v = woff[lane];
        int sv = v;
#pragma unroll
        for (int o = 1; o < 32; o <<= 1) {
            int u = __shfl_up_sync(0xFFFFFFFFu, sv, o);
            if (lane >= o) sv += u;
        }
        woff[lane] = sv - v;   // exclusive
    }
    __syncthreads();

    // pass 2: emit offsets (coalesced)
    int run = woff[w];
#pragma unroll
    for (int j = 0; j < 49; j++) {
        int i = base + j * 32 + lane;
        int c = (i < n) ? (int)g_degcnt[i].y : 0;
        int sc = c;
#pragma unroll
        for (int o = 1; o < 32; o <<= 1) {
            int u = __shfl_up_sync(0xFFFFFFFFu, sc, o);
            if (lane >= o) sc += u;
        }
        if (i < n) g_off[i] = run + sc - c;
        run += __shfl_sync(0xFFFFFFFFu, sc, 31);
    }
}

// ---------------- CSR fill; coef computed inline ----------------
__global__ void k_fill(const int* __restrict__ rows, const int* __restrict__ cols,
                       const float* __restrict__ ew, const int* __restrict__ nid, int E) {
    int e = blockIdx.x * blockDim.x + threadIdx.x;
    if (e >= E) return;
    int r = rows[e], c = cols[e];
    float coef = rsqrtf(g_degcnt[r].x + 1.0f) * ew[e] * rsqrtf(g_degcnt[c].x + 1.0f);
    int p = g_off[c] + atomicAdd(&g_pos[c], 1);
    int cb = __float_as_int(coef);
    g_adj [p] = make_int2(r,      cb);
    g_adj1[p] = make_int2(nid[r], cb);
}

// ---------------- helpers ----------------
__device__ __forceinline__ float4 unpack_h4(uint2 v) {
    __half2 a = *(__half2*)&v.x;
    __half2 b = *(__half2*)&v.y;
    float2 f01 = __half22float2(a), f23 = __half22float2(b);
    return make_float4(f01.x, f01.y, f23.x, f23.y);
}

union H2U { __half2 h; unsigned int u; };

// ------- layer 1 fused: aggregate from fp16 G1 table (L1-resident) + residual(emb) + LN
__global__ void k_agg1(const int* __restrict__ nid, const float* __restrict__ emb,
                       const float* __restrict__ b,
                       const float* __restrict__ gamma, const float* __restrict__ beta,
                       float* __restrict__ out, int n) {
    int gt = blockIdx.x * blockDim.x + threadIdx.x;
    int node = gt >> 5, lane = gt & 31;
    if (node >= n) return;
    int id = nid[node];
    float cself = 1.0f / (1.0f + g_degcnt[node].x);
    float4 hv = unpack_h4(g_G1h[id * D4 + lane]);
    float4 bv = ((const float4*)b)[lane];
    float4 acc = make_float4(fmaf(cself, hv.x, bv.x), fmaf(cself, hv.y, bv.y),
                             fmaf(cself, hv.z, bv.z), fmaf(cself, hv.w, bv.w));
    int off = g_off[node], deg = g_pos[node];
    const int2* __restrict__ adj = g_adj1 + off;
    int j = 0;
    for (; j + 3 < deg; j += 4) {
        int2 a0 = adj[j], a1 = adj[j+1], a2 = adj[j+2], a3 = adj[j+3];
        float4 h0 = unpack_h4(g_G1h[a0.x * D4 + lane]);
        float4 h1 = unpack_h4(g_G1h[a1.x * D4 + lane]);
        float4 h2 = unpack_h4(g_G1h[a2.x * D4 + lane]);
        float4 h3 = unpack_h4(g_G1h[a3.x * D4 + lane]);
        float c0 = __int_as_float(a0.y), c1 = __int_as_float(a1.y);
        float c2 = __int_as_float(a2.y), c3 = __int_as_float(a3.y);
        acc.x = fmaf(c0,h0.x,acc.x); acc.y = fmaf(c0,h0.y,acc.y); acc.z = fmaf(c0,h0.z,acc.z); acc.w = fmaf(c0,h0.w,acc.w);
        acc.x = fmaf(c1,h1.x,acc.x); acc.y = fmaf(c1,h1.y,acc.y); acc.z = fmaf(c1,h1.z,acc.z); acc.w = fmaf(c1,h1.w,acc.w);
        acc.x = fmaf(c2,h2.x,acc.x); acc.y = fmaf(c2,h2.y,acc.y); acc.z = fmaf(c2,h2.z,acc.z); acc.w = fmaf(c2,h2.w,acc.w);
        acc.x = fmaf(c3,h3.x,acc.x); acc.y = fmaf(c3,h3.y,acc.y); acc.z = fmaf(c3,h3.z,acc.z); acc.w = fmaf(c3,h3.w,acc.w);
    }
    for (; j < deg; j++) {
        int2 a0 = adj[j];
        float c0 = __int_as_float(a0.y);
        float4 h0 = unpack_h4(g_G1h[a0.x * D4 + lane]);
        acc.x = fmaf(c0,h0.x,acc.x); acc.y = fmaf(c0,h0.y,acc.y); acc.z = fmaf(c0,h0.z,acc.z); acc.w = fmaf(c0,h0.w,acc.w);
    }
    float4 xv = ((const float4*)emb)[id * D4 + lane];
    acc.x += xv.x; acc.y += xv.y; acc.z += xv.z; acc.w += xv.w;
    float s  = acc.x + acc.y + acc.z + acc.w;
    float sq = acc.x*acc.x + acc.y*acc.y + acc.z*acc.z + acc.w*acc.w;
#pragma unroll
    for (int o = 16; o > 0; o >>= 1) {
        s  += __shfl_xor_sync(0xFFFFFFFFu, s,  o);
        sq += __shfl_xor_sync(0xFFFFFFFFu, sq, o);
    }
    float mu  = s * (1.f / D);
    float var = sq * (1.f / D) - mu * mu;
    float rs  = rsqrtf(var + LN_EPS);
    float4 g  = ((const float4*)gamma)[lane];
    float4 be = ((const float4*)beta )[lane];
    float4 o;
    o.x = (acc.x - mu) * rs * g.x + be.x;
    o.y = (acc.y - mu) * rs * g.y + be.y;
    o.z = (acc.z - mu) * rs * g.z + be.z;
    o.w = (acc.w - mu) * rs * g.w + be.w;
    ((float4*)out)[node * D4 + lane] = o;
}

// ------- layer 2 fused: gather fp16 h + residual + LN; epilogue restores zeros -------
__global__ void k_agg2(const float* __restrict__ x, const float* __restrict__ b,
                       const float* __restrict__ gamma, const float* __restrict__ beta,
                       float* __restrict__ out, int n) {
    int gt = blockIdx.x * blockDim.x + threadIdx.x;
    int node = gt >> 5, lane = gt & 31;
    if (node >= n) return;
    float cself = 1.0f / (1.0f + g_degcnt[node].x);
    float4 hv = unpack_h4(g_h16[node * D4 + lane]);
    float4 bv = ((const float4*)b)[lane];
    float4 acc = make_float4(fmaf(cself, hv.x, bv.x), fmaf(cself, hv.y, bv.y),
                             fmaf(cself, hv.z, bv.z), fmaf(cself, hv.w, bv.w));
    int off = g_off[node], deg = g_pos[node];
    const int2* __restrict__ adj = g_adj + off;
    int j = 0;
    for (; j + 3 < deg; j += 4) {
        int2 a0 = adj[j], a1 = adj[j+1], a2 = adj[j+2], a3 = adj[j+3];
        float4 h0 = unpack_h4(g_h16[a0.x * D4 + lane]);
        float4 h1 = unpack_h4(g_h16[a1.x * D4 + lane]);
        float4 h2 = unpack_h4(g_h16[a2.x * D4 + lane]);
        float4 h3 = unpack_h4(g_h16[a3.x * D4 + lane]);
        float c0 = __int_as_float(a0.y), c1 = __int_as_float(a1.y);
        float c2 = __int_as_float(a2.y), c3 = __int_as_float(a3.y);
        acc.x = fmaf(c0,h0.x,acc.x); acc.y = fmaf(c0,h0.y,acc.y); acc.z = fmaf(c0,h0.z,acc.z); acc.w = fmaf(c0,h0.w,acc.w);
        acc.x = fmaf(c1,h1.x,acc.x); acc.y = fmaf(c1,h1.y,acc.y); acc.z = fmaf(c1,h1.z,acc.z); acc.w = fmaf(c1,h1.w,acc.w);
        acc.x = fmaf(c2,h2.x,acc.x); acc.y = fmaf(c2,h2.y,acc.y); acc.z = fmaf(c2,h2.z,acc.z); acc.w = fmaf(c2,h2.w,acc.w);
        acc.x = fmaf(c3,h3.x,acc.x); acc.y = fmaf(c3,h3.y,acc.y); acc.z = fmaf(c3,h3.z,acc.z); acc.w = fmaf(c3,h3.w,acc.w);
    }
    for (; j < deg; j++) {
        int2 a0 = adj[j];
        float c0 = __int_as_float(a0.y);
        float4 h0 = unpack_h4(g_h16[a0.x * D4 + lane]);
        acc.x = fmaf(c0,h0.x,acc.x); acc.y = fmaf(c0,h0.y,acc.y); acc.z = fmaf(c0,h0.z,acc.z); acc.w = fmaf(c0,h0.w,acc.w);
    }
    float4 xv = ((const float4*)x)[node * D4 + lane];
    acc.x += xv.x; acc.y += xv.y; acc.z += xv.z; acc.w += xv.w;
    float s  = acc.x + acc.y + acc.z + acc.w;
    float sq = acc.x*acc.x + acc.y*acc.y + acc.z*acc.z + acc.w*acc.w;
#pragma unroll
    for (int o = 16; o > 0; o >>= 1) {
        s  += __shfl_xor_sync(0xFFFFFFFFu, s,  o);
        sq += __shfl_xor_sync(0xFFFFFFFFu, sq, o);
    }
    float mu  = s * (1.f / D);
    float var = sq * (1.f / D) - mu * mu;
    float rs  = rsqrtf(var + LN_EPS);
    float4 g  = ((const float4*)gamma)[lane];
    float4 be = ((const float4*)beta )[lane];
    float4 o;
    o.x = (acc.x - mu) * rs * g.x + be.x;
    o.y = (acc.y - mu) * rs * g.y + be.y;
    o.z = (acc.z - mu) * rs * g.z + be.z;
    o.w = (acc.w - mu) * rs * g.w + be.w;
    ((float4*)out)[node * D4 + lane] = o;
    if (lane == 0) {                 // restore replay-invariant state
        g_degcnt[node] = make_float2(0.0f, 0.0f);
        g_pos[node] = 0;
    }
}

// ---------------- GEMM: H(fp16) = X(fp32) @ W with packed fma.rn.f32x2 ----------------
typedef unsigned long long ull;

__device__ __forceinline__ ull pk2(float a) {
    ull r; asm("mov.b64 %0, {%1, %1};" : "=l"(r) : "f"(a)); return r;
}
__device__ __forceinline__ void fma2(ull& d, ull a, ull b) {
    asm("fma.rn.f32x2 %0, %1, %2, %0;" : "+l"(d) : "l"(a), "l"(b));
}

#define XS_PITCH 136
#define GEMM_SMEM (64 * XS_PITCH * 4 + 128 * 128 * 4)

__global__ void __launch_bounds__(256) k_gemm(const float* __restrict__ X,
                                              const float* __restrict__ W,
                                              uint2* __restrict__ H, int n) {
    extern __shared__ float smem[];
    float* Xs = smem;                    // [64][XS_PITCH]
    float* Ws = smem + 64 * XS_PITCH;    // [128][128]

    int t  = threadIdx.x;
    int m0 = blockIdx.x * 64;

    const float4* W4  = (const float4*)W;
    float4*       Ws4 = (float4*)Ws;
#pragma unroll
    for (int i = 0; i < 16; i++) Ws4[t + i * 256] = W4[t + i * 256];

#pragma unroll
    for (int i = 0; i < 8; i++) {
        int idx = t + i * 256;
        int r = idx >> 5, kc = idx & 31;
        float4 v = make_float4(0.f, 0.f, 0.f, 0.f);
        if (m0 + r < n) v = ((const float4*)X)[(m0 + r) * D4 + kc];
        *(float4*)&Xs[r * XS_PITCH + kc * 4] = v;
    }
    __syncthreads();

    int cg = t & 15;
    int rg = t >> 4;

    ull acc[4][4];
#pragma unroll
    for (int i = 0; i < 4; i++)
#pragma unroll
        for (int j = 0; j < 4; j++) acc[i][j] = 0ull;

#pragma unroll 2
    for (int k0 = 0; k0 < D; k0 += 4) {
        float4 A[4];
#pragma unroll
        for (int i = 0; i < 4; i++)
            A[i] = *(const float4*)&Xs[(rg * 4 + i) * XS_PITCH + k0];
#pragma unroll
        for (int kk = 0; kk < 4; kk++) {
            ulonglong2 w0 = *(const ulonglong2*)&Ws[(k0 + kk) * D + cg * 4];
            ulonglong2 w1 = *(const ulonglong2*)&Ws[(k0 + kk) * D + 64 + cg * 4];
#pragma unroll
            for (int i = 0; i < 4; i++) {
                float av = (kk == 0) ? A[i].x : (kk == 1) ? A[i].y
                         : (kk == 2) ? A[i].z : A[i].w;
                ull ap = pk2(av);
                fma2(acc[i][0], ap, w0.x);
                fma2(acc[i][1], ap, w0.y);
                fma2(acc[i][2], ap, w1.x);
                fma2(acc[i][3], ap, w1.y);
            }
        }
    }

    union Cv { ull u; float2 f; };
#pragma unroll
    for (int i = 0; i < 4; i++) {
        int row = m0 + rg * 4 + i;
        if (row < n) {
            Cv c0, c1, c2, c3;
            c0.u = acc[i][0]; c1.u = acc[i][1]; c2.u = acc[i][2]; c3.u = acc[i][3];
            H2U p0, p1, p2, p3;
            p0.h = __floats2half2_rn(c0.f.x, c0.f.y);
            p1.h = __floats2half2_rn(c1.f.x, c1.f.y);
            p2.h = __floats2half2_rn(c2.f.x, c2.f.y);
            p3.h = __floats2half2_rn(c3.f.x, c3.f.y);
            uint2 o0, o1;
            o0.x = p0.u; o0.y = p1.u;
            o1.x = p2.u; o1.y = p3.u;
            H[row * D4 + cg]      = o0;
            H[row * D4 + 16 + cg] = o1;
        }
    }
}

// ---------------- host launch ----------------
extern "C" void kernel_launch(void* const* d_in, const int* in_sizes, int n_in,
                              void* d_out, int out_size) {
    const int*   node_ids = (const int*)  d_in[0];
    const int*   edge_idx = (const int*)  d_in[1];
    const float* edge_w   = (const float*)d_in[2];
    const float* emb      = (const float*)d_in[3];
    const float* W1       = (const float*)d_in[4];
    const float* b1       = (const float*)d_in[5];
    const float* W2       = (const float*)d_in[6];
    const float* b2       = (const float*)d_in[7];
    const float* gamma1   = (const float*)d_in[8];
    const float* beta1    = (const float*)d_in[9];
    const float* gamma2   = (const float*)d_in[10];
    const float* beta2    = (const float*)d_in[11];
    float* out = (float*)d_out;

    const int n = in_sizes[0];
    const int E = in_sizes[1] / 2;
    const int* rows = edge_idx;
    const int* cols = edge_idx + E;

    static bool attr_done = false;
    if (!attr_done) {
        cudaFuncSetAttribute(k_gemm, cudaFuncAttributeMaxDynamicSharedMemorySize, GEMM_SMEM);
        attr_done = true;
    }

    float *d_x;
    uint2 *d_h16, *d_G1h;
    cudaGetSymbolAddress((void**)&d_x,   g_x);
    cudaGetSymbolAddress((void**)&d_h16, g_h16);
    cudaGetSymbolAddress((void**)&d_G1h, g_G1h);

    const int nodeBlocks = (n * 32 + 255) / 256;

    // (1) independent small GEMM first: G1 = emb @ W1 (fp16 out)
    k_gemm <<<(VOCAB + 63) / 64, 256, GEMM_SMEM>>>(emb, W1, d_G1h, VOCAB);

    // (2-4) CSR build
    k_count<<<(E + 255) / 256, 256>>>(cols, edge_w, E);
    k_scan <<<1, 1024>>>(n);
    k_fill <<<(E + 255) / 256, 256>>>(rows, cols, edge_w, node_ids, E);

    // (5) layer 1 fused
    k_agg1 <<<nodeBlocks, 256>>>(node_ids, emb, b1, gamma1, beta1, d_x, n);

    // (6) layer 2 GEMM
    k_gemm <<<(n + 63) / 64, 256, GEMM_SMEM>>>(d_x, W2, d_h16, n);

    // (7) layer 2 fused + state restore
    k_agg2 <<<nodeBlocks, 256>>>(d_x, b2, gamma2, beta2, out, n);
}